// round 8
// baseline (speedup 1.0000x reference)
#include <cuda_runtime.h>
#include <cuda_fp16.h>
#include <math.h>
#include <cstdint>

// Problem constants
#define HID 2048
#define INTER 1024
#define NEXP 8
#define NTOK 2048
#define TOPK 2
#define NPAIR (NTOK * TOPK)   // 4096

#define TM 128                // pair-rows per tile
#define KC 32                 // K halves per chunk (64B per logical row)

// ---------------- device scratch ----------------
__device__ int    g_cnt[NEXP];
__device__ int    g_tok[NEXP * NPAIR];    // PAIR index per bucket slot
__device__ float  g_wt[NEXP * NPAIR];
__device__ int4   g_desc[64];             // {expert, row_start, count, inter_base}
__device__ int    g_ntiles;
__device__ __half gh_x[NTOK * HID];
__device__ __half gh_gate[NEXP * INTER * HID];
__device__ __half gh_up[NEXP * INTER * HID];
__device__ __half gh_down[NEXP * HID * INTER];
__device__ __half g_inter[(NPAIR + TM) * INTER];
__device__ float  g_out2[NPAIR * HID];    // 33.5 MB per-pair down output

// ---------------- helpers ----------------
__device__ __forceinline__ void ldm4(unsigned& r0, unsigned& r1, unsigned& r2,
                                     unsigned& r3, const void* ptr) {
    unsigned addr = (unsigned)__cvta_generic_to_shared(ptr);
    asm volatile("ldmatrix.sync.aligned.m8n8.x4.shared.b16 {%0,%1,%2,%3}, [%4];"
                 : "=r"(r0), "=r"(r1), "=r"(r2), "=r"(r3) : "r"(addr));
}

#define MMA_F16(c, a, b0, b1)                                                 \
    asm volatile(                                                             \
        "mma.sync.aligned.m16n8k16.row.col.f32.f16.f16.f32 "                  \
        "{%0,%1,%2,%3}, {%4,%5,%6,%7}, {%8,%9}, {%0,%1,%2,%3};"               \
        : "+f"((c)[0]), "+f"((c)[1]), "+f"((c)[2]), "+f"((c)[3])              \
        : "r"((a)[0]), "r"((a)[1]), "r"((a)[2]), "r"((a)[3]), "r"(b0), "r"(b1))

#define CP16(dst, src)                                                        \
    asm volatile("cp.async.cg.shared.global [%0], [%1], 16;"                  \
                 :: "r"(dst), "l"(src))
#define CP_COMMIT() asm volatile("cp.async.commit_group;" ::: "memory")
#define CP_WAIT1()  asm volatile("cp.async.wait_group 1;" ::: "memory")

// Paired-row XOR swizzle: (row, 16B-group g in 0..3) -> uint4 index.
__device__ __forceinline__ int swzi(int row, int g) {
    int srow = row >> 1;
    return srow * 8 + ((((row & 1) << 2) | g) ^ (srow & 7));
}

// ---------------- kernel 0: init counters ----------------
__global__ void k_init() {
    if (threadIdx.x < NEXP) g_cnt[threadIdx.x] = 0;
}

// ---------------- kernel 1: route (store PAIR index) ----------------
__global__ void k_route(const int* __restrict__ idx,
                        const float* __restrict__ wts) {
    int p = blockIdx.x * blockDim.x + threadIdx.x;
    if (p >= NPAIR) return;
    int e = idx[p] & 7;
    float w = wts[p];
    int pos = atomicAdd(&g_cnt[e], 1);
    g_tok[e * NPAIR + pos] = p;       // pair index; token = p >> 1
    g_wt[e * NPAIR + pos] = w;
}

// ---------------- kernel 2: tile descriptors ----------------
__global__ void k_desc() {
    if (threadIdx.x != 0 || blockIdx.x != 0) return;
    int nt = 0, base = 0;
    for (int e = 0; e < NEXP; e++) {
        int c = g_cnt[e];
        for (int s = 0; s < c; s += TM) {
            int rows = c - s; if (rows > TM) rows = TM;
            g_desc[nt] = make_int4(e, s, rows, base + s);
            nt++;
        }
        base += c;
    }
    g_ntiles = nt;
}

// ---------------- kernel: fp32 -> fp16 pre-convert (weights + x) ----------
__global__ void k_cvtall(const float4* __restrict__ gate,
                         const float4* __restrict__ up,
                         const float4* __restrict__ down,
                         const float4* __restrict__ x) {
    const int NW8 = NEXP * INTER * HID / 8;
    const int NX8 = NTOK * HID / 8;
    int total = 3 * NW8 + NX8;
    for (int i = blockIdx.x * blockDim.x + threadIdx.x; i < total;
         i += gridDim.x * blockDim.x) {
        const float4* src; uint4* dst; int j;
        if (i < NW8)          { src = gate; dst = (uint4*)gh_gate; j = i; }
        else if (i < 2 * NW8) { src = up;   dst = (uint4*)gh_up;   j = i - NW8; }
        else if (i < 3 * NW8) { src = down; dst = (uint4*)gh_down; j = i - 2 * NW8; }
        else                  { src = x;    dst = (uint4*)gh_x;    j = i - 3 * NW8; }
        float4 f0 = src[2 * j], f1 = src[2 * j + 1];
        __half2 h0 = __floats2half2_rn(f0.x, f0.y);
        __half2 h1 = __floats2half2_rn(f0.z, f0.w);
        __half2 h2 = __floats2half2_rn(f1.x, f1.y);
        __half2 h3 = __floats2half2_rn(f1.z, f1.w);
        uint4 o;
        o.x = *(unsigned*)&h0; o.y = *(unsigned*)&h1;
        o.z = *(unsigned*)&h2; o.w = *(unsigned*)&h3;
        dst[j] = o;
    }
}

// ---------------- kernel 3: fp16 MMA gate+up + SwiGLU ----------------
#define GU_A(s)  (0 + (s) * 512)
#define GU_G(s)  (1536 + (s) * 512)
#define GU_U(s)  (3072 + (s) * 512)
#define GU_TOKB  (4608 * 16)
#define GU_SMEM  (4608 * 16 + TM * 8 + 16)

__global__ __launch_bounds__(512, 1) void k_gateup() {
    int tile = blockIdx.y;
    if (tile >= g_ntiles) return;
    int4 d = g_desc[tile];
    int e = d.x, rs = d.y, cnt = d.z, ib = d.w;
    int ctile = blockIdx.x * 128;

    extern __shared__ uint4 smem[];
    int*   s_tok = (int*)((char*)smem + GU_TOKB);
    float* s_w   = (float*)(s_tok + TM);

    int tid = threadIdx.x, lane = tid & 31, warp = tid >> 5;
    if (tid < TM) {
        s_tok[tid] = (tid < cnt) ? g_tok[e * NPAIR + rs + tid] : g_tok[e * NPAIR + rs];
        s_w[tid]   = (tid < cnt) ? g_wt[e * NPAIR + rs + tid] : 0.0f;
    }
    __syncthreads();

    int prow = tid >> 2, pg = tid & 3;
    const __half* aptr = gh_x + (size_t)(s_tok[prow] >> 1) * HID + pg * 8;
    const __half* gptr = gh_gate + (size_t)e * INTER * HID + (size_t)(ctile + prow) * HID + pg * 8;
    const __half* uptr = gh_up   + (size_t)e * INTER * HID + (size_t)(ctile + prow) * HID + pg * 8;
    int swp = swzi(prow, pg);
    unsigned sbase = (unsigned)__cvta_generic_to_shared(smem);

    int mg = (warp & 3) * 32, nh = (warp >> 2) * 32;
    int ly = lane >> 2, lx = lane & 3;
    int arl = (lane & 7) + ((lane >> 3) & 1) * 8;
    int akb = (lane >> 4) & 1;
    int brl = (lane & 7) + ((lane >> 4) & 1) * 8;
    int bkb = (lane >> 3) & 1;

    float accg[2][4][4] = {}, accu[2][4][4] = {};

    const int NCH = HID / KC;   // 64
    #pragma unroll
    for (int s = 0; s < 2; s++) {
        int ko = s * KC;
        CP16(sbase + (GU_A(s) + swp) * 16, aptr + ko);
        CP16(sbase + (GU_G(s) + swp) * 16, gptr + ko);
        CP16(sbase + (GU_U(s) + swp) * 16, uptr + ko);
        CP_COMMIT();
    }

    for (int c = 0; c < NCH; c++) {
        int p = c % 3;
        CP_WAIT1();
        __syncthreads();

        const uint4* bA = smem + GU_A(p);
        const uint4* bG = smem + GU_G(p);
        const uint4* bU = smem + GU_U(p);
        #pragma unroll
        for (int ks = 0; ks < 2; ks++) {
            int kg = ks * 2;
            unsigned a[2][4], b[2][4];
            ldm4(a[0][0], a[0][1], a[0][2], a[0][3], bA + swzi(mg + arl,      kg + akb));
            ldm4(a[1][0], a[1][1], a[1][2], a[1][3], bA + swzi(mg + 16 + arl, kg + akb));
            ldm4(b[0][0], b[0][1], b[0][2], b[0][3], bG + swzi(nh + brl,      kg + bkb));
            ldm4(b[1][0], b[1][1], b[1][2], b[1][3], bG + swzi(nh + 16 + brl, kg + bkb));
            #pragma unroll
            for (int mi = 0; mi < 2; mi++) {
                MMA_F16(accg[mi][0], a[mi], b[0][0], b[0][1]);
                MMA_F16(accg[mi][1], a[mi], b[0][2], b[0][3]);
                MMA_F16(accg[mi][2], a[mi], b[1][0], b[1][1]);
                MMA_F16(accg[mi][3], a[mi], b[1][2], b[1][3]);
            }
            ldm4(b[0][0], b[0][1], b[0][2], b[0][3], bU + swzi(nh + brl,      kg + bkb));
            ldm4(b[1][0], b[1][1], b[1][2], b[1][3], bU + swzi(nh + 16 + brl, kg + bkb));
            #pragma unroll
            for (int mi = 0; mi < 2; mi++) {
                MMA_F16(accu[mi][0], a[mi], b[0][0], b[0][1]);
                MMA_F16(accu[mi][1], a[mi], b[0][2], b[0][3]);
                MMA_F16(accu[mi][2], a[mi], b[1][0], b[1][1]);
                MMA_F16(accu[mi][3], a[mi], b[1][2], b[1][3]);
            }
        }
        if (c + 2 < NCH) {
            int s = (c + 2) % 3;
            int ko = (c + 2) * KC;
            CP16(sbase + (GU_A(s) + swp) * 16, aptr + ko);
            CP16(sbase + (GU_G(s) + swp) * 16, gptr + ko);
            CP16(sbase + (GU_U(s) + swp) * 16, uptr + ko);
        }
        CP_COMMIT();
    }

    #pragma unroll
    for (int mi = 0; mi < 2; mi++) {
        int r0 = mg + mi * 16 + ly, r1 = r0 + 8;
        #pragma unroll
        for (int nj = 0; nj < 4; nj++) {
            int cc = ctile + nh + nj * 8 + 2 * lx;
            if (r0 < cnt) {
                float w = s_w[r0];
                float ga = accg[mi][nj][0], ua = accu[mi][nj][0];
                float gb = accg[mi][nj][1], ub = accu[mi][nj][1];
                float o0 = ga / (1.0f + __expf(-ga)) * ua * w;
                float o1 = gb / (1.0f + __expf(-gb)) * ub * w;
                *(__half2*)&g_inter[(size_t)(ib + r0) * INTER + cc] = __floats2half2_rn(o0, o1);
            }
            if (r1 < cnt) {
                float w = s_w[r1];
                float ga = accg[mi][nj][2], ua = accu[mi][nj][2];
                float gb = accg[mi][nj][3], ub = accu[mi][nj][3];
                float o0 = ga / (1.0f + __expf(-ga)) * ua * w;
                float o1 = gb / (1.0f + __expf(-gb)) * ub * w;
                *(__half2*)&g_inter[(size_t)(ib + r1) * INTER + cc] = __floats2half2_rn(o0, o1);
            }
        }
    }
}

// ---------------- kernel 4: fp16 MMA down + per-pair STG ----------------
#define DN_A(s)  (0 + (s) * 512)
#define DN_B(s)  (1536 + (s) * 512)
#define DN_TOKB  (3072 * 16)
#define DN_SMEM  (3072 * 16 + TM * 4 + 16)

__global__ __launch_bounds__(512, 1) void k_down() {
    int tile = blockIdx.y;
    if (tile >= g_ntiles) return;
    int4 d = g_desc[tile];
    int e = d.x, rs = d.y, cnt = d.z, ib = d.w;
    int ctile = blockIdx.x * 128;

    extern __shared__ uint4 smem[];
    int* s_tok = (int*)((char*)smem + DN_TOKB);

    int tid = threadIdx.x, lane = tid & 31, warp = tid >> 5;
    if (tid < TM)
        s_tok[tid] = (tid < cnt) ? g_tok[e * NPAIR + rs + tid] : 0;
    __syncthreads();

    int prow = tid >> 2, pg = tid & 3;
    const __half* aptr = g_inter + (size_t)(ib + prow) * INTER + pg * 8;
    const __half* bptr = gh_down + (size_t)e * HID * INTER + (size_t)(ctile + prow) * INTER + pg * 8;
    int swp = swzi(prow, pg);
    unsigned sbase = (unsigned)__cvta_generic_to_shared(smem);

    int mg = (warp & 3) * 32, nh = (warp >> 2) * 32;
    int ly = lane >> 2, lx = lane & 3;
    int arl = (lane & 7) + ((lane >> 3) & 1) * 8;
    int akb = (lane >> 4) & 1;
    int brl = (lane & 7) + ((lane >> 4) & 1) * 8;
    int bkb = (lane >> 3) & 1;

    float acc[2][4][4] = {};

    const int NCH = INTER / KC;   // 32
    #pragma unroll
    for (int s = 0; s < 2; s++) {
        int ko = s * KC;
        CP16(sbase + (DN_A(s) + swp) * 16, aptr + ko);
        CP16(sbase + (DN_B(s) + swp) * 16, bptr + ko);
        CP_COMMIT();
    }

    for (int c = 0; c < NCH; c++) {
        int p = c % 3;
        CP_WAIT1();
        __syncthreads();

        const uint4* bA = smem + DN_A(p);
        const uint4* bB = smem + DN_B(p);
        #pragma unroll
        for (int ks = 0; ks < 2; ks++) {
            int kg = ks * 2;
            unsigned a[2][4], b[2][4];
            ldm4(a[0][0], a[0][1], a[0][2], a[0][3], bA + swzi(mg + arl,      kg + akb));
            ldm4(a[1][0], a[1][1], a[1][2], a[1][3], bA + swzi(mg + 16 + arl, kg + akb));
            ldm4(b[0][0], b[0][1], b[0][2], b[0][3], bB + swzi(nh + brl,      kg + bkb));
            ldm4(b[1][0], b[1][1], b[1][2], b[1][3], bB + swzi(nh + 16 + brl, kg + bkb));
            #pragma unroll
            for (int mi = 0; mi < 2; mi++) {
                MMA_F16(acc[mi][0], a[mi], b[0][0], b[0][1]);
                MMA_F16(acc[mi][1], a[mi], b[0][2], b[0][3]);
                MMA_F16(acc[mi][2], a[mi], b[1][0], b[1][1]);
                MMA_F16(acc[mi][3], a[mi], b[1][2], b[1][3]);
            }
        }
        if (c + 2 < NCH) {
            int s = (c + 2) % 3;
            int ko = (c + 2) * KC;
            CP16(sbase + (DN_A(s) + swp) * 16, aptr + ko);
            CP16(sbase + (DN_B(s) + swp) * 16, bptr + ko);
        }
        CP_COMMIT();
    }

    // epilogue: plain STG per pair (no atomics; pairs owned exclusively)
    #pragma unroll
    for (int mi = 0; mi < 2; mi++) {
        int r0 = mg + mi * 16 + ly, r1 = r0 + 8;
        #pragma unroll
        for (int nj = 0; nj < 4; nj++) {
            int cc = ctile + nh + nj * 8 + 2 * lx;
            if (r0 < cnt) {
                float* o = g_out2 + (size_t)s_tok[r0] * HID + cc;
                *(float2*)o = make_float2(acc[mi][nj][0], acc[mi][nj][1]);
            }
            if (r1 < cnt) {
                float* o = g_out2 + (size_t)s_tok[r1] * HID + cc;
                *(float2*)o = make_float2(acc[mi][nj][2], acc[mi][nj][3]);
            }
        }
    }
}

// ---------------- kernel 5: reduce pairs -> tokens ----------------
__global__ void k_reduce(float4* __restrict__ out) {
    const int H4 = HID / 4;
    int total = NTOK * H4;
    const float4* o2 = (const float4*)g_out2;
    for (int i = blockIdx.x * blockDim.x + threadIdx.x; i < total;
         i += gridDim.x * blockDim.x) {
        int t = i / H4, j = i % H4;
        float4 a = o2[(size_t)(2 * t) * H4 + j];
        float4 b = o2[(size_t)(2 * t + 1) * H4 + j];
        out[i] = make_float4(a.x + b.x, a.y + b.y, a.z + b.z, a.w + b.w);
    }
}

// ---------------- launch ----------------
extern "C" void kernel_launch(void* const* d_in, const int* in_sizes, int n_in,
                              void* d_out, int out_size) {
    const float* x    = (const float*)d_in[0];
    const int*   eidx = (const int*)d_in[1];
    const float* ewt  = (const float*)d_in[2];
    const float* gate = (const float*)d_in[3];
    const float* up   = (const float*)d_in[4];
    const float* down = (const float*)d_in[5];
    float* out = (float*)d_out;

    cudaFuncSetAttribute(k_gateup, cudaFuncAttributeMaxDynamicSharedMemorySize, GU_SMEM);
    cudaFuncSetAttribute(k_down,   cudaFuncAttributeMaxDynamicSharedMemorySize, DN_SMEM);

    k_init<<<1, 32>>>();
    k_route<<<(NPAIR + 255) / 256, 256>>>(eidx, ewt);
    k_desc<<<1, 32>>>();
    k_cvtall<<<8192, 256>>>((const float4*)gate, (const float4*)up,
                            (const float4*)down, (const float4*)x);

    dim3 g2(INTER / 128, 40);
    k_gateup<<<g2, 512, GU_SMEM>>>();

    dim3 g3(HID / 128, 40);
    k_down<<<g3, 512, DN_SMEM>>>();

    k_reduce<<<1024, 256>>>((float4*)out);
}

// round 9
// speedup vs baseline: 1.4463x; 1.4463x over previous
#include <cuda_runtime.h>
#include <cuda_fp16.h>
#include <math.h>
#include <cstdint>

// Problem constants
#define HID 2048
#define INTER 1024
#define NEXP 8
#define NTOK 2048
#define TOPK 2
#define NPAIR (NTOK * TOPK)   // 4096

#define TM 64                 // pair-rows per tile
#define KC 32                 // K halves per chunk (64B per logical row)

// ---------------- device scratch ----------------
__device__ int    g_cnt[NEXP];
__device__ int    g_tok[NEXP * NPAIR];
__device__ float  g_wt[NEXP * NPAIR];
__device__ int4   g_desc[96];             // {expert, row_start, count, inter_base}
__device__ int    g_ntiles;
__device__ __half gh_x[NTOK * HID];
__device__ __half gh_gate[NEXP * INTER * HID];
__device__ __half gh_up[NEXP * INTER * HID];
__device__ __half gh_down[NEXP * HID * INTER];
__device__ __half g_inter[(NPAIR + TM) * INTER];

// ---------------- helpers ----------------
__device__ __forceinline__ void ldm4(unsigned& r0, unsigned& r1, unsigned& r2,
                                     unsigned& r3, const void* ptr) {
    unsigned addr = (unsigned)__cvta_generic_to_shared(ptr);
    asm volatile("ldmatrix.sync.aligned.m8n8.x4.shared.b16 {%0,%1,%2,%3}, [%4];"
                 : "=r"(r0), "=r"(r1), "=r"(r2), "=r"(r3) : "r"(addr));
}

#define MMA_F16(c, a, b0, b1)                                                 \
    asm volatile(                                                             \
        "mma.sync.aligned.m16n8k16.row.col.f32.f16.f16.f32 "                  \
        "{%0,%1,%2,%3}, {%4,%5,%6,%7}, {%8,%9}, {%0,%1,%2,%3};"               \
        : "+f"((c)[0]), "+f"((c)[1]), "+f"((c)[2]), "+f"((c)[3])              \
        : "r"((a)[0]), "r"((a)[1]), "r"((a)[2]), "r"((a)[3]), "r"(b0), "r"(b1))

#define CP16(dst, src)                                                        \
    asm volatile("cp.async.cg.shared.global [%0], [%1], 16;"                  \
                 :: "r"(dst), "l"(src))
#define CP_COMMIT() asm volatile("cp.async.commit_group;" ::: "memory")
#define CP_WAIT1()  asm volatile("cp.async.wait_group 1;" ::: "memory")

// Paired-row XOR swizzle: (row, 16B-group g in 0..3) -> uint4 index.
// Conflict-free for cp.async STS and all ldmatrix phases.
__device__ __forceinline__ int swzi(int row, int g) {
    int srow = row >> 1;
    return srow * 8 + ((((row & 1) << 2) | g) ^ (srow & 7));
}

// ---------------- kernel 0: zero output + counters ----------------
__global__ void k_zero(float* out) {
    int i = blockIdx.x * blockDim.x + threadIdx.x;
    int total = NTOK * HID;
    for (; i < total; i += gridDim.x * blockDim.x) out[i] = 0.0f;
    if (blockIdx.x == 0 && threadIdx.x < NEXP) g_cnt[threadIdx.x] = 0;
}

// ---------------- kernel 1: route ----------------
__global__ void k_route(const int* __restrict__ idx,
                        const float* __restrict__ wts) {
    int p = blockIdx.x * blockDim.x + threadIdx.x;
    if (p >= NPAIR) return;
    int e = idx[p] & 7;
    float w = wts[p];
    int pos = atomicAdd(&g_cnt[e], 1);
    g_tok[e * NPAIR + pos] = p >> 1;   // token id
    g_wt[e * NPAIR + pos] = w;
}

// ---------------- kernel 2: tile descriptors (64-row tiles) ----------------
__global__ void k_desc() {
    if (threadIdx.x != 0 || blockIdx.x != 0) return;
    int nt = 0, base = 0;
    for (int e = 0; e < NEXP; e++) {
        int c = g_cnt[e];
        for (int s = 0; s < c; s += TM) {
            int rows = c - s; if (rows > TM) rows = TM;
            g_desc[nt] = make_int4(e, s, rows, base + s);
            nt++;
        }
        base += c;
    }
    g_ntiles = nt;
}

// ---------------- kernel: fp32 -> fp16 pre-convert (weights + x) ----------
__global__ void k_cvtall(const float4* __restrict__ gate,
                         const float4* __restrict__ up,
                         const float4* __restrict__ down,
                         const float4* __restrict__ x) {
    const int NW8 = NEXP * INTER * HID / 8;
    const int NX8 = NTOK * HID / 8;
    int total = 3 * NW8 + NX8;
    for (int i = blockIdx.x * blockDim.x + threadIdx.x; i < total;
         i += gridDim.x * blockDim.x) {
        const float4* src; uint4* dst; int j;
        if (i < NW8)          { src = gate; dst = (uint4*)gh_gate; j = i; }
        else if (i < 2 * NW8) { src = up;   dst = (uint4*)gh_up;   j = i - NW8; }
        else if (i < 3 * NW8) { src = down; dst = (uint4*)gh_down; j = i - 2 * NW8; }
        else                  { src = x;    dst = (uint4*)gh_x;    j = i - 3 * NW8; }
        float4 f0 = src[2 * j], f1 = src[2 * j + 1];
        __half2 h0 = __floats2half2_rn(f0.x, f0.y);
        __half2 h1 = __floats2half2_rn(f0.z, f0.w);
        __half2 h2 = __floats2half2_rn(f1.x, f1.y);
        __half2 h3 = __floats2half2_rn(f1.z, f1.w);
        uint4 o;
        o.x = *(unsigned*)&h0; o.y = *(unsigned*)&h1;
        o.z = *(unsigned*)&h2; o.w = *(unsigned*)&h3;
        dst[j] = o;
    }
}

// ---------------- kernel 3: fp16 MMA gate+up + SwiGLU ----------------
// Block 64 pairs x 128 inter cols, 256 threads (2m x 4n warps, 32x32 each
// for BOTH gate and up), 2 CTAs/SM. 3-stage cp.async pipeline.
// smem layout (uint4 units): A[3][256] | G[3][512] | U[3][512]
#define GU_A(s)  (0 + (s) * 256)
#define GU_G(s)  (768 + (s) * 512)
#define GU_U(s)  (2304 + (s) * 512)
#define GU_TOKB  (3840 * 16)
#define GU_SMEM  (3840 * 16 + TM * 8 + 16)

__global__ __launch_bounds__(256, 2) void k_gateup() {
    int tile = blockIdx.y;
    if (tile >= g_ntiles) return;
    int4 d = g_desc[tile];
    int e = d.x, rs = d.y, cnt = d.z, ib = d.w;
    int ctile = blockIdx.x * 128;

    extern __shared__ uint4 smem[];
    int*   s_tok = (int*)((char*)smem + GU_TOKB);
    float* s_w   = (float*)(s_tok + TM);

    int tid = threadIdx.x, lane = tid & 31, warp = tid >> 5;
    if (tid < TM) {
        s_tok[tid] = (tid < cnt) ? g_tok[e * NPAIR + rs + tid] : g_tok[e * NPAIR + rs];
        s_w[tid]   = (tid < cnt) ? g_wt[e * NPAIR + rs + tid] : 0.0f;
    }
    __syncthreads();

    // producer: A rows 0..63 (1 cp), G/U rows prow & prow+64 (2 cp each)
    int prow = tid >> 2, pg = tid & 3;
    const __half* aptr = gh_x + (size_t)s_tok[prow] * HID + pg * 8;
    const __half* gp0 = gh_gate + (size_t)e * INTER * HID + (size_t)(ctile + prow) * HID + pg * 8;
    const __half* gp1 = gp0 + (size_t)64 * HID;
    const __half* up0 = gh_up + (size_t)e * INTER * HID + (size_t)(ctile + prow) * HID + pg * 8;
    const __half* up1 = up0 + (size_t)64 * HID;
    int sw_lo = swzi(prow, pg);
    int sw_hi = swzi(prow + 64, pg);
    unsigned sbase = (unsigned)__cvta_generic_to_shared(smem);

    // consumer mapping: 2 m-warps x 4 n-warps
    int mg = (warp & 1) * 32, nh = (warp >> 1) * 32;
    int ly = lane >> 2, lx = lane & 3;
    int arl = (lane & 7) + ((lane >> 3) & 1) * 8;
    int akb = (lane >> 4) & 1;
    int brl = (lane & 7) + ((lane >> 4) & 1) * 8;
    int bkb = (lane >> 3) & 1;

    float accg[2][4][4] = {}, accu[2][4][4] = {};

    const int NCH = HID / KC;   // 64
    #pragma unroll
    for (int s = 0; s < 2; s++) {
        int ko = s * KC;
        CP16(sbase + (GU_A(s) + sw_lo) * 16, aptr + ko);
        CP16(sbase + (GU_G(s) + sw_lo) * 16, gp0 + ko);
        CP16(sbase + (GU_G(s) + sw_hi) * 16, gp1 + ko);
        CP16(sbase + (GU_U(s) + sw_lo) * 16, up0 + ko);
        CP16(sbase + (GU_U(s) + sw_hi) * 16, up1 + ko);
        CP_COMMIT();
    }

    for (int c = 0; c < NCH; c++) {
        int p = c % 3;
        CP_WAIT1();
        __syncthreads();

        const uint4* bA = smem + GU_A(p);
        const uint4* bG = smem + GU_G(p);
        const uint4* bU = smem + GU_U(p);
        #pragma unroll
        for (int ks = 0; ks < 2; ks++) {
            int kg = ks * 2;
            unsigned a[2][4], b[2][4];
            ldm4(a[0][0], a[0][1], a[0][2], a[0][3], bA + swzi(mg + arl,      kg + akb));
            ldm4(a[1][0], a[1][1], a[1][2], a[1][3], bA + swzi(mg + 16 + arl, kg + akb));
            ldm4(b[0][0], b[0][1], b[0][2], b[0][3], bG + swzi(nh + brl,      kg + bkb));
            ldm4(b[1][0], b[1][1], b[1][2], b[1][3], bG + swzi(nh + 16 + brl, kg + bkb));
            #pragma unroll
            for (int mi = 0; mi < 2; mi++) {
                MMA_F16(accg[mi][0], a[mi], b[0][0], b[0][1]);
                MMA_F16(accg[mi][1], a[mi], b[0][2], b[0][3]);
                MMA_F16(accg[mi][2], a[mi], b[1][0], b[1][1]);
                MMA_F16(accg[mi][3], a[mi], b[1][2], b[1][3]);
            }
            ldm4(b[0][0], b[0][1], b[0][2], b[0][3], bU + swzi(nh + brl,      kg + bkb));
            ldm4(b[1][0], b[1][1], b[1][2], b[1][3], bU + swzi(nh + 16 + brl, kg + bkb));
            #pragma unroll
            for (int mi = 0; mi < 2; mi++) {
                MMA_F16(accu[mi][0], a[mi], b[0][0], b[0][1]);
                MMA_F16(accu[mi][1], a[mi], b[0][2], b[0][3]);
                MMA_F16(accu[mi][2], a[mi], b[1][0], b[1][1]);
                MMA_F16(accu[mi][3], a[mi], b[1][2], b[1][3]);
            }
        }
        if (c + 2 < NCH) {
            int s = (c + 2) % 3;
            int ko = (c + 2) * KC;
            CP16(sbase + (GU_A(s) + sw_lo) * 16, aptr + ko);
            CP16(sbase + (GU_G(s) + sw_lo) * 16, gp0 + ko);
            CP16(sbase + (GU_G(s) + sw_hi) * 16, gp1 + ko);
            CP16(sbase + (GU_U(s) + sw_lo) * 16, up0 + ko);
            CP16(sbase + (GU_U(s) + sw_hi) * 16, up1 + ko);
        }
        CP_COMMIT();
    }

    // epilogue: silu(g)*u*w -> g_inter (fp16)
    #pragma unroll
    for (int mi = 0; mi < 2; mi++) {
        int r0 = mg + mi * 16 + ly, r1 = r0 + 8;
        #pragma unroll
        for (int nj = 0; nj < 4; nj++) {
            int cc = ctile + nh + nj * 8 + 2 * lx;
            if (r0 < cnt) {
                float w = s_w[r0];
                float ga = accg[mi][nj][0], ua = accu[mi][nj][0];
                float gb = accg[mi][nj][1], ub = accu[mi][nj][1];
                float o0 = ga / (1.0f + __expf(-ga)) * ua * w;
                float o1 = gb / (1.0f + __expf(-gb)) * ub * w;
                *(__half2*)&g_inter[(size_t)(ib + r0) * INTER + cc] = __floats2half2_rn(o0, o1);
            }
            if (r1 < cnt) {
                float w = s_w[r1];
                float ga = accg[mi][nj][2], ua = accu[mi][nj][2];
                float gb = accg[mi][nj][3], ub = accu[mi][nj][3];
                float o0 = ga / (1.0f + __expf(-ga)) * ua * w;
                float o1 = gb / (1.0f + __expf(-gb)) * ub * w;
                *(__half2*)&g_inter[(size_t)(ib + r1) * INTER + cc] = __floats2half2_rn(o0, o1);
            }
        }
    }
}

// ---------------- kernel 4: fp16 MMA down + scatter-add ----------------
// Block 64 pairs x 128 hid cols, 256 threads, 2 CTAs/SM. 3-stage cp.async.
#define DN_A(s)  (0 + (s) * 256)
#define DN_B(s)  (768 + (s) * 512)
#define DN_TOKB  (2304 * 16)
#define DN_SMEM  (2304 * 16 + TM * 4 + 16)

__global__ __launch_bounds__(256, 2) void k_down(float* __restrict__ out) {
    int tile = blockIdx.y;
    if (tile >= g_ntiles) return;
    int4 d = g_desc[tile];
    int e = d.x, rs = d.y, cnt = d.z, ib = d.w;
    int ctile = blockIdx.x * 128;

    extern __shared__ uint4 smem[];
    int* s_tok = (int*)((char*)smem + DN_TOKB);

    int tid = threadIdx.x, lane = tid & 31, warp = tid >> 5;
    if (tid < TM)
        s_tok[tid] = (tid < cnt) ? g_tok[e * NPAIR + rs + tid] : 0;
    __syncthreads();

    int prow = tid >> 2, pg = tid & 3;
    const __half* aptr = g_inter + (size_t)(ib + prow) * INTER + pg * 8;
    const __half* bp0 = gh_down + (size_t)e * HID * INTER + (size_t)(ctile + prow) * INTER + pg * 8;
    const __half* bp1 = bp0 + (size_t)64 * INTER;
    int sw_lo = swzi(prow, pg);
    int sw_hi = swzi(prow + 64, pg);
    unsigned sbase = (unsigned)__cvta_generic_to_shared(smem);

    int mg = (warp & 1) * 32, nh = (warp >> 1) * 32;
    int ly = lane >> 2, lx = lane & 3;
    int arl = (lane & 7) + ((lane >> 3) & 1) * 8;
    int akb = (lane >> 4) & 1;
    int brl = (lane & 7) + ((lane >> 4) & 1) * 8;
    int bkb = (lane >> 3) & 1;

    float acc[2][4][4] = {};

    const int NCH = INTER / KC;   // 32
    #pragma unroll
    for (int s = 0; s < 2; s++) {
        int ko = s * KC;
        CP16(sbase + (DN_A(s) + sw_lo) * 16, aptr + ko);
        CP16(sbase + (DN_B(s) + sw_lo) * 16, bp0 + ko);
        CP16(sbase + (DN_B(s) + sw_hi) * 16, bp1 + ko);
        CP_COMMIT();
    }

    for (int c = 0; c < NCH; c++) {
        int p = c % 3;
        CP_WAIT1();
        __syncthreads();

        const uint4* bA = smem + DN_A(p);
        const uint4* bB = smem + DN_B(p);
        #pragma unroll
        for (int ks = 0; ks < 2; ks++) {
            int kg = ks * 2;
            unsigned a[2][4], b[2][4];
            ldm4(a[0][0], a[0][1], a[0][2], a[0][3], bA + swzi(mg + arl,      kg + akb));
            ldm4(a[1][0], a[1][1], a[1][2], a[1][3], bA + swzi(mg + 16 + arl, kg + akb));
            ldm4(b[0][0], b[0][1], b[0][2], b[0][3], bB + swzi(nh + brl,      kg + bkb));
            ldm4(b[1][0], b[1][1], b[1][2], b[1][3], bB + swzi(nh + 16 + brl, kg + bkb));
            #pragma unroll
            for (int mi = 0; mi < 2; mi++) {
                MMA_F16(acc[mi][0], a[mi], b[0][0], b[0][1]);
                MMA_F16(acc[mi][1], a[mi], b[0][2], b[0][3]);
                MMA_F16(acc[mi][2], a[mi], b[1][0], b[1][1]);
                MMA_F16(acc[mi][3], a[mi], b[1][2], b[1][3]);
            }
        }
        if (c + 2 < NCH) {
            int s = (c + 2) % 3;
            int ko = (c + 2) * KC;
            CP16(sbase + (DN_A(s) + sw_lo) * 16, aptr + ko);
            CP16(sbase + (DN_B(s) + sw_lo) * 16, bp0 + ko);
            CP16(sbase + (DN_B(s) + sw_hi) * 16, bp1 + ko);
        }
        CP_COMMIT();
    }

    #pragma unroll
    for (int mi = 0; mi < 2; mi++) {
        int r0 = mg + mi * 16 + ly, r1 = r0 + 8;
        #pragma unroll
        for (int nj = 0; nj < 4; nj++) {
            int cc = ctile + nh + nj * 8 + 2 * lx;
            if (r0 < cnt) {
                float* o = out + (size_t)s_tok[r0] * HID + cc;
                atomicAdd(o,     acc[mi][nj][0]);
                atomicAdd(o + 1, acc[mi][nj][1]);
            }
            if (r1 < cnt) {
                float* o = out + (size_t)s_tok[r1] * HID + cc;
                atomicAdd(o,     acc[mi][nj][2]);
                atomicAdd(o + 1, acc[mi][nj][3]);
            }
        }
    }
}

// ---------------- launch ----------------
extern "C" void kernel_launch(void* const* d_in, const int* in_sizes, int n_in,
                              void* d_out, int out_size) {
    const float* x    = (const float*)d_in[0];
    const int*   eidx = (const int*)d_in[1];
    const float* ewt  = (const float*)d_in[2];
    const float* gate = (const float*)d_in[3];
    const float* up   = (const float*)d_in[4];
    const float* down = (const float*)d_in[5];
    float* out = (float*)d_out;

    cudaFuncSetAttribute(k_gateup, cudaFuncAttributeMaxDynamicSharedMemorySize, GU_SMEM);
    cudaFuncSetAttribute(k_down,   cudaFuncAttributeMaxDynamicSharedMemorySize, DN_SMEM);

    k_zero<<<2048, 256>>>(out);
    k_route<<<(NPAIR + 255) / 256, 256>>>(eidx, ewt);
    k_desc<<<1, 32>>>();
    k_cvtall<<<8192, 256>>>((const float4*)gate, (const float4*)up,
                            (const float4*)down, (const float4*)x);

    // max tiles = 4096/64 + 7 = 71 -> 72
    dim3 g2(INTER / 128, 72);
    k_gateup<<<g2, 256, GU_SMEM>>>();

    dim3 g3(HID / 128, 72);
    k_down<<<g3, 256, DN_SMEM>>>(out);
}

// round 10
// speedup vs baseline: 1.4489x; 1.0018x over previous
#include <cuda_runtime.h>
#include <cuda_fp16.h>
#include <math.h>
#include <cstdint>

// Problem constants
#define HID 2048
#define INTER 1024
#define NEXP 8
#define NTOK 2048
#define TOPK 2
#define NPAIR (NTOK * TOPK)   // 4096

#define TM 64                 // pair-rows per tile
#define KC 32                 // K halves per chunk (64B per logical row)

// ---------------- device scratch ----------------
__device__ int    g_cnt[NEXP];
__device__ int    g_tok[NEXP * NPAIR];
__device__ float  g_wt[NEXP * NPAIR];
__device__ int4   g_desc[96];             // {expert, row_start, count, inter_base}
__device__ int    g_ntiles;
__device__ __half gh_x[NTOK * HID];
__device__ __half gh_gate[NEXP * INTER * HID];
__device__ __half gh_up[NEXP * INTER * HID];
__device__ __half gh_down[NEXP * HID * INTER];
__device__ __half g_inter[(NPAIR + TM) * INTER];

// ---------------- helpers ----------------
__device__ __forceinline__ void ldm4(unsigned& r0, unsigned& r1, unsigned& r2,
                                     unsigned& r3, const void* ptr) {
    unsigned addr = (unsigned)__cvta_generic_to_shared(ptr);
    asm volatile("ldmatrix.sync.aligned.m8n8.x4.shared.b16 {%0,%1,%2,%3}, [%4];"
                 : "=r"(r0), "=r"(r1), "=r"(r2), "=r"(r3) : "r"(addr));
}

#define MMA_F16(c, a, b0, b1)                                                 \
    asm volatile(                                                             \
        "mma.sync.aligned.m16n8k16.row.col.f32.f16.f16.f32 "                  \
        "{%0,%1,%2,%3}, {%4,%5,%6,%7}, {%8,%9}, {%0,%1,%2,%3};"               \
        : "+f"((c)[0]), "+f"((c)[1]), "+f"((c)[2]), "+f"((c)[3])              \
        : "r"((a)[0]), "r"((a)[1]), "r"((a)[2]), "r"((a)[3]), "r"(b0), "r"(b1))

#define CP16(dst, src)                                                        \
    asm volatile("cp.async.cg.shared.global [%0], [%1], 16;"                  \
                 :: "r"(dst), "l"(src))
#define CP_COMMIT() asm volatile("cp.async.commit_group;" ::: "memory")
#define CP_WAIT1()  asm volatile("cp.async.wait_group 1;" ::: "memory")

// Paired-row XOR swizzle: (row, 16B-group g in 0..3) -> uint4 index.
__device__ __forceinline__ int swzi(int row, int g) {
    int srow = row >> 1;
    return srow * 8 + ((((row & 1) << 2) | g) ^ (srow & 7));
}

// ---------------- small setup kernels ----------------
__global__ void k_cnt0() {
    if (threadIdx.x < NEXP) g_cnt[threadIdx.x] = 0;
}

__global__ void k_zero_out(float4* out) {
    int i = blockIdx.x * blockDim.x + threadIdx.x;
    int total = NTOK * HID / 4;
    for (; i < total; i += gridDim.x * blockDim.x)
        out[i] = make_float4(0.f, 0.f, 0.f, 0.f);
}

__global__ void k_route(const int* __restrict__ idx,
                        const float* __restrict__ wts) {
    int p = blockIdx.x * blockDim.x + threadIdx.x;
    if (p >= NPAIR) return;
    int e = idx[p] & 7;
    float w = wts[p];
    int pos = atomicAdd(&g_cnt[e], 1);
    g_tok[e * NPAIR + pos] = p >> 1;   // token id
    g_wt[e * NPAIR + pos] = w;
}

__global__ void k_desc() {
    if (threadIdx.x != 0 || blockIdx.x != 0) return;
    int nt = 0, base = 0;
    for (int e = 0; e < NEXP; e++) {
        int c = g_cnt[e];
        for (int s = 0; s < c; s += TM) {
            int rows = c - s; if (rows > TM) rows = TM;
            g_desc[nt] = make_int4(e, s, rows, base + s);
            nt++;
        }
        base += c;
    }
    g_ntiles = nt;
}

// ---------------- cvt kernels (split by consumer) ----------------
__device__ __forceinline__ void cvt8(const float4* src, uint4* dst, int j) {
    float4 f0 = src[2 * j], f1 = src[2 * j + 1];
    __half2 h0 = __floats2half2_rn(f0.x, f0.y);
    __half2 h1 = __floats2half2_rn(f0.z, f0.w);
    __half2 h2 = __floats2half2_rn(f1.x, f1.y);
    __half2 h3 = __floats2half2_rn(f1.z, f1.w);
    uint4 o;
    o.x = *(unsigned*)&h0; o.y = *(unsigned*)&h1;
    o.z = *(unsigned*)&h2; o.w = *(unsigned*)&h3;
    dst[j] = o;
}

// gate + up + x (feeds k_gateup)
__global__ void k_cvt_gux(const float4* __restrict__ gate,
                          const float4* __restrict__ up,
                          const float4* __restrict__ x) {
    const int NW8 = NEXP * INTER * HID / 8;
    const int NX8 = NTOK * HID / 8;
    int total = 2 * NW8 + NX8;
    for (int i = blockIdx.x * blockDim.x + threadIdx.x; i < total;
         i += gridDim.x * blockDim.x) {
        if (i < NW8)          cvt8(gate, (uint4*)gh_gate, i);
        else if (i < 2 * NW8) cvt8(up,   (uint4*)gh_up,   i - NW8);
        else                  cvt8(x,    (uint4*)gh_x,    i - 2 * NW8);
    }
}

// down (feeds k_down; overlapped with k_gateup on side stream)
__global__ void k_cvt_down(const float4* __restrict__ down) {
    const int NW8 = NEXP * INTER * HID / 8;
    for (int i = blockIdx.x * blockDim.x + threadIdx.x; i < NW8;
         i += gridDim.x * blockDim.x)
        cvt8(down, (uint4*)gh_down, i);
}

// ---------------- kernel 3: fp16 MMA gate+up + SwiGLU (unchanged) --------
#define GU_A(s)  (0 + (s) * 256)
#define GU_G(s)  (768 + (s) * 512)
#define GU_U(s)  (2304 + (s) * 512)
#define GU_TOKB  (3840 * 16)
#define GU_SMEM  (3840 * 16 + TM * 8 + 16)

__global__ __launch_bounds__(256, 2) void k_gateup() {
    int tile = blockIdx.y;
    if (tile >= g_ntiles) return;
    int4 d = g_desc[tile];
    int e = d.x, rs = d.y, cnt = d.z, ib = d.w;
    int ctile = blockIdx.x * 128;

    extern __shared__ uint4 smem[];
    int*   s_tok = (int*)((char*)smem + GU_TOKB);
    float* s_w   = (float*)(s_tok + TM);

    int tid = threadIdx.x, lane = tid & 31, warp = tid >> 5;
    if (tid < TM) {
        s_tok[tid] = (tid < cnt) ? g_tok[e * NPAIR + rs + tid] : g_tok[e * NPAIR + rs];
        s_w[tid]   = (tid < cnt) ? g_wt[e * NPAIR + rs + tid] : 0.0f;
    }
    __syncthreads();

    int prow = tid >> 2, pg = tid & 3;
    const __half* aptr = gh_x + (size_t)s_tok[prow] * HID + pg * 8;
    const __half* gp0 = gh_gate + (size_t)e * INTER * HID + (size_t)(ctile + prow) * HID + pg * 8;
    const __half* gp1 = gp0 + (size_t)64 * HID;
    const __half* up0 = gh_up + (size_t)e * INTER * HID + (size_t)(ctile + prow) * HID + pg * 8;
    const __half* up1 = up0 + (size_t)64 * HID;
    int sw_lo = swzi(prow, pg);
    int sw_hi = swzi(prow + 64, pg);
    unsigned sbase = (unsigned)__cvta_generic_to_shared(smem);

    int mg = (warp & 1) * 32, nh = (warp >> 1) * 32;
    int ly = lane >> 2, lx = lane & 3;
    int arl = (lane & 7) + ((lane >> 3) & 1) * 8;
    int akb = (lane >> 4) & 1;
    int brl = (lane & 7) + ((lane >> 4) & 1) * 8;
    int bkb = (lane >> 3) & 1;

    float accg[2][4][4] = {}, accu[2][4][4] = {};

    const int NCH = HID / KC;   // 64
    #pragma unroll
    for (int s = 0; s < 2; s++) {
        int ko = s * KC;
        CP16(sbase + (GU_A(s) + sw_lo) * 16, aptr + ko);
        CP16(sbase + (GU_G(s) + sw_lo) * 16, gp0 + ko);
        CP16(sbase + (GU_G(s) + sw_hi) * 16, gp1 + ko);
        CP16(sbase + (GU_U(s) + sw_lo) * 16, up0 + ko);
        CP16(sbase + (GU_U(s) + sw_hi) * 16, up1 + ko);
        CP_COMMIT();
    }

    for (int c = 0; c < NCH; c++) {
        int p = c % 3;
        CP_WAIT1();
        __syncthreads();

        const uint4* bA = smem + GU_A(p);
        const uint4* bG = smem + GU_G(p);
        const uint4* bU = smem + GU_U(p);
        #pragma unroll
        for (int ks = 0; ks < 2; ks++) {
            int kg = ks * 2;
            unsigned a[2][4], b[2][4];
            ldm4(a[0][0], a[0][1], a[0][2], a[0][3], bA + swzi(mg + arl,      kg + akb));
            ldm4(a[1][0], a[1][1], a[1][2], a[1][3], bA + swzi(mg + 16 + arl, kg + akb));
            ldm4(b[0][0], b[0][1], b[0][2], b[0][3], bG + swzi(nh + brl,      kg + bkb));
            ldm4(b[1][0], b[1][1], b[1][2], b[1][3], bG + swzi(nh + 16 + brl, kg + bkb));
            #pragma unroll
            for (int mi = 0; mi < 2; mi++) {
                MMA_F16(accg[mi][0], a[mi], b[0][0], b[0][1]);
                MMA_F16(accg[mi][1], a[mi], b[0][2], b[0][3]);
                MMA_F16(accg[mi][2], a[mi], b[1][0], b[1][1]);
                MMA_F16(accg[mi][3], a[mi], b[1][2], b[1][3]);
            }
            ldm4(b[0][0], b[0][1], b[0][2], b[0][3], bU + swzi(nh + brl,      kg + bkb));
            ldm4(b[1][0], b[1][1], b[1][2], b[1][3], bU + swzi(nh + 16 + brl, kg + bkb));
            #pragma unroll
            for (int mi = 0; mi < 2; mi++) {
                MMA_F16(accu[mi][0], a[mi], b[0][0], b[0][1]);
                MMA_F16(accu[mi][1], a[mi], b[0][2], b[0][3]);
                MMA_F16(accu[mi][2], a[mi], b[1][0], b[1][1]);
                MMA_F16(accu[mi][3], a[mi], b[1][2], b[1][3]);
            }
        }
        if (c + 2 < NCH) {
            int s = (c + 2) % 3;
            int ko = (c + 2) * KC;
            CP16(sbase + (GU_A(s) + sw_lo) * 16, aptr + ko);
            CP16(sbase + (GU_G(s) + sw_lo) * 16, gp0 + ko);
            CP16(sbase + (GU_G(s) + sw_hi) * 16, gp1 + ko);
            CP16(sbase + (GU_U(s) + sw_lo) * 16, up0 + ko);
            CP16(sbase + (GU_U(s) + sw_hi) * 16, up1 + ko);
        }
        CP_COMMIT();
    }

    #pragma unroll
    for (int mi = 0; mi < 2; mi++) {
        int r0 = mg + mi * 16 + ly, r1 = r0 + 8;
        #pragma unroll
        for (int nj = 0; nj < 4; nj++) {
            int cc = ctile + nh + nj * 8 + 2 * lx;
            if (r0 < cnt) {
                float w = s_w[r0];
                float ga = accg[mi][nj][0], ua = accu[mi][nj][0];
                float gb = accg[mi][nj][1], ub = accu[mi][nj][1];
                float o0 = ga / (1.0f + __expf(-ga)) * ua * w;
                float o1 = gb / (1.0f + __expf(-gb)) * ub * w;
                *(__half2*)&g_inter[(size_t)(ib + r0) * INTER + cc] = __floats2half2_rn(o0, o1);
            }
            if (r1 < cnt) {
                float w = s_w[r1];
                float ga = accg[mi][nj][2], ua = accu[mi][nj][2];
                float gb = accg[mi][nj][3], ub = accu[mi][nj][3];
                float o0 = ga / (1.0f + __expf(-ga)) * ua * w;
                float o1 = gb / (1.0f + __expf(-gb)) * ub * w;
                *(__half2*)&g_inter[(size_t)(ib + r1) * INTER + cc] = __floats2half2_rn(o0, o1);
            }
        }
    }
}

// ---------------- kernel 4: fp16 MMA down + scatter-add (unchanged) ------
#define DN_A(s)  (0 + (s) * 256)
#define DN_B(s)  (768 + (s) * 512)
#define DN_TOKB  (2304 * 16)
#define DN_SMEM  (2304 * 16 + TM * 4 + 16)

__global__ __launch_bounds__(256, 2) void k_down(float* __restrict__ out) {
    int tile = blockIdx.y;
    if (tile >= g_ntiles) return;
    int4 d = g_desc[tile];
    int e = d.x, rs = d.y, cnt = d.z, ib = d.w;
    int ctile = blockIdx.x * 128;

    extern __shared__ uint4 smem[];
    int* s_tok = (int*)((char*)smem + DN_TOKB);

    int tid = threadIdx.x, lane = tid & 31, warp = tid >> 5;
    if (tid < TM)
        s_tok[tid] = (tid < cnt) ? g_tok[e * NPAIR + rs + tid] : 0;
    __syncthreads();

    int prow = tid >> 2, pg = tid & 3;
    const __half* aptr = g_inter + (size_t)(ib + prow) * INTER + pg * 8;
    const __half* bp0 = gh_down + (size_t)e * HID * INTER + (size_t)(ctile + prow) * INTER + pg * 8;
    const __half* bp1 = bp0 + (size_t)64 * INTER;
    int sw_lo = swzi(prow, pg);
    int sw_hi = swzi(prow + 64, pg);
    unsigned sbase = (unsigned)__cvta_generic_to_shared(smem);

    int mg = (warp & 1) * 32, nh = (warp >> 1) * 32;
    int ly = lane >> 2, lx = lane & 3;
    int arl = (lane & 7) + ((lane >> 3) & 1) * 8;
    int akb = (lane >> 4) & 1;
    int brl = (lane & 7) + ((lane >> 4) & 1) * 8;
    int bkb = (lane >> 3) & 1;

    float acc[2][4][4] = {};

    const int NCH = INTER / KC;   // 32
    #pragma unroll
    for (int s = 0; s < 2; s++) {
        int ko = s * KC;
        CP16(sbase + (DN_A(s) + sw_lo) * 16, aptr + ko);
        CP16(sbase + (DN_B(s) + sw_lo) * 16, bp0 + ko);
        CP16(sbase + (DN_B(s) + sw_hi) * 16, bp1 + ko);
        CP_COMMIT();
    }

    for (int c = 0; c < NCH; c++) {
        int p = c % 3;
        CP_WAIT1();
        __syncthreads();

        const uint4* bA = smem + DN_A(p);
        const uint4* bB = smem + DN_B(p);
        #pragma unroll
        for (int ks = 0; ks < 2; ks++) {
            int kg = ks * 2;
            unsigned a[2][4], b[2][4];
            ldm4(a[0][0], a[0][1], a[0][2], a[0][3], bA + swzi(mg + arl,      kg + akb));
            ldm4(a[1][0], a[1][1], a[1][2], a[1][3], bA + swzi(mg + 16 + arl, kg + akb));
            ldm4(b[0][0], b[0][1], b[0][2], b[0][3], bB + swzi(nh + brl,      kg + bkb));
            ldm4(b[1][0], b[1][1], b[1][2], b[1][3], bB + swzi(nh + 16 + brl, kg + bkb));
            #pragma unroll
            for (int mi = 0; mi < 2; mi++) {
                MMA_F16(acc[mi][0], a[mi], b[0][0], b[0][1]);
                MMA_F16(acc[mi][1], a[mi], b[0][2], b[0][3]);
                MMA_F16(acc[mi][2], a[mi], b[1][0], b[1][1]);
                MMA_F16(acc[mi][3], a[mi], b[1][2], b[1][3]);
            }
        }
        if (c + 2 < NCH) {
            int s = (c + 2) % 3;
            int ko = (c + 2) * KC;
            CP16(sbase + (DN_A(s) + sw_lo) * 16, aptr + ko);
            CP16(sbase + (DN_B(s) + sw_lo) * 16, bp0 + ko);
            CP16(sbase + (DN_B(s) + sw_hi) * 16, bp1 + ko);
        }
        CP_COMMIT();
    }

    #pragma unroll
    for (int mi = 0; mi < 2; mi++) {
        int r0 = mg + mi * 16 + ly, r1 = r0 + 8;
        #pragma unroll
        for (int nj = 0; nj < 4; nj++) {
            int cc = ctile + nh + nj * 8 + 2 * lx;
            if (r0 < cnt) {
                float* o = out + (size_t)s_tok[r0] * HID + cc;
                atomicAdd(o,     acc[mi][nj][0]);
                atomicAdd(o + 1, acc[mi][nj][1]);
            }
            if (r1 < cnt) {
                float* o = out + (size_t)s_tok[r1] * HID + cc;
                atomicAdd(o,     acc[mi][nj][2]);
                atomicAdd(o + 1, acc[mi][nj][3]);
            }
        }
    }
}

// ---------------- launch: forked capture graph ----------------
extern "C" void kernel_launch(void* const* d_in, const int* in_sizes, int n_in,
                              void* d_out, int out_size) {
    const float* x    = (const float*)d_in[0];
    const int*   eidx = (const int*)d_in[1];
    const float* ewt  = (const float*)d_in[2];
    const float* gate = (const float*)d_in[3];
    const float* up   = (const float*)d_in[4];
    const float* down = (const float*)d_in[5];
    float* out = (float*)d_out;

    cudaFuncSetAttribute(k_gateup, cudaFuncAttributeMaxDynamicSharedMemorySize, GU_SMEM);
    cudaFuncSetAttribute(k_down,   cudaFuncAttributeMaxDynamicSharedMemorySize, DN_SMEM);

    // side stream + fork/join events (created per call; kernel_launch is only
    // invoked for correctness + capture, so the handful of leaked handles is
    // harmless and avoids destroy-during-capture hazards)
    cudaStream_t s2;
    cudaStreamCreateWithFlags(&s2, cudaStreamNonBlocking);
    cudaEvent_t eFork, eJoin;
    cudaEventCreateWithFlags(&eFork, cudaEventDisableTiming);
    cudaEventCreateWithFlags(&eJoin, cudaEventDisableTiming);

    // fork: side branch does work only k_down needs
    cudaEventRecord(eFork, 0);
    cudaStreamWaitEvent(s2, eFork, 0);
    k_zero_out<<<2048, 256, 0, s2>>>((float4*)out);
    k_cvt_down<<<4096, 256, 0, s2>>>((const float4*)down);
    cudaEventRecord(eJoin, s2);

    // main branch: routing + gate/up/x cvt + gateup GEMM
    k_cnt0<<<1, 32>>>();
    k_route<<<(NPAIR + 255) / 256, 256>>>(eidx, ewt);
    k_desc<<<1, 32>>>();
    k_cvt_gux<<<8192, 256>>>((const float4*)gate, (const float4*)up,
                             (const float4*)x);

    dim3 g2(INTER / 128, 72);
    k_gateup<<<g2, 256, GU_SMEM>>>();

    // join: down needs zeroed out + converted down-weights + g_inter
    cudaStreamWaitEvent(0, eJoin, 0);
    dim3 g3(HID / 128, 72);
    k_down<<<g3, 256, DN_SMEM>>>(out);
}

// round 11
// speedup vs baseline: 1.5371x; 1.0609x over previous
#include <cuda_runtime.h>
#include <cuda_fp16.h>
#include <math.h>
#include <cstdint>

// Problem constants
#define HID 2048
#define INTER 1024
#define NEXP 8
#define NTOK 2048
#define TOPK 2
#define NPAIR (NTOK * TOPK)   // 4096

#define TM 64                 // pair-rows per tile
#define KC 32                 // K halves per chunk (64B per logical row)

// ---------------- device scratch ----------------
__device__ int    g_cnt[NEXP];
__device__ int    g_tok[NEXP * NPAIR];
__device__ float  g_wt[NEXP * NPAIR];
__device__ int4   g_desc[96];             // {expert, row_start, count, inter_base}
__device__ int    g_ntiles;
__device__ __half gh_x[NTOK * HID];
__device__ __half gh_gate[NEXP * INTER * HID];
__device__ __half gh_up[NEXP * INTER * HID];
__device__ __half gh_down[NEXP * HID * INTER];
__device__ __half g_inter[(NPAIR + TM) * INTER];

// ---------------- helpers ----------------
__device__ __forceinline__ void ldm4(unsigned& r0, unsigned& r1, unsigned& r2,
                                     unsigned& r3, const void* ptr) {
    unsigned addr = (unsigned)__cvta_generic_to_shared(ptr);
    asm volatile("ldmatrix.sync.aligned.m8n8.x4.shared.b16 {%0,%1,%2,%3}, [%4];"
                 : "=r"(r0), "=r"(r1), "=r"(r2), "=r"(r3) : "r"(addr));
}

#define MMA_F16(c, a, b0, b1)                                                 \
    asm volatile(                                                             \
        "mma.sync.aligned.m16n8k16.row.col.f32.f16.f16.f32 "                  \
        "{%0,%1,%2,%3}, {%4,%5,%6,%7}, {%8,%9}, {%0,%1,%2,%3};"               \
        : "+f"((c)[0]), "+f"((c)[1]), "+f"((c)[2]), "+f"((c)[3])              \
        : "r"((a)[0]), "r"((a)[1]), "r"((a)[2]), "r"((a)[3]), "r"(b0), "r"(b1))

#define CP16(dst, src)                                                        \
    asm volatile("cp.async.cg.shared.global [%0], [%1], 16;"                  \
                 :: "r"(dst), "l"(src))
#define CP_COMMIT() asm volatile("cp.async.commit_group;" ::: "memory")
#define CP_WAIT1()  asm volatile("cp.async.wait_group 1;" ::: "memory")

// Paired-row XOR swizzle: (row, 16B-group g in 0..3) -> uint4 index.
__device__ __forceinline__ int swzi(int row, int g) {
    int srow = row >> 1;
    return srow * 8 + ((((row & 1) << 2) | g) ^ (srow & 7));
}

// ---------------- small setup kernels ----------------
__global__ void k_cnt0() {
    if (threadIdx.x < NEXP) g_cnt[threadIdx.x] = 0;
}

__global__ void k_zero_out(float4* out) {
    int i = blockIdx.x * blockDim.x + threadIdx.x;
    int total = NTOK * HID / 4;
    for (; i < total; i += gridDim.x * blockDim.x)
        out[i] = make_float4(0.f, 0.f, 0.f, 0.f);
}

__global__ void k_route(const int* __restrict__ idx,
                        const float* __restrict__ wts) {
    int p = blockIdx.x * blockDim.x + threadIdx.x;
    if (p >= NPAIR) return;
    int e = idx[p] & 7;
    float w = wts[p];
    int pos = atomicAdd(&g_cnt[e], 1);
    g_tok[e * NPAIR + pos] = p >> 1;   // token id
    g_wt[e * NPAIR + pos] = w;
}

__global__ void k_desc() {
    if (threadIdx.x != 0 || blockIdx.x != 0) return;
    int nt = 0, base = 0;
    for (int e = 0; e < NEXP; e++) {
        int c = g_cnt[e];
        for (int s = 0; s < c; s += TM) {
            int rows = c - s; if (rows > TM) rows = TM;
            g_desc[nt] = make_int4(e, s, rows, base + s);
            nt++;
        }
        base += c;
    }
    g_ntiles = nt;
}

// ---------------- cvt kernels (split by consumer) ----------------
__device__ __forceinline__ void cvt8(const float4* src, uint4* dst, int j) {
    float4 f0 = src[2 * j], f1 = src[2 * j + 1];
    __half2 h0 = __floats2half2_rn(f0.x, f0.y);
    __half2 h1 = __floats2half2_rn(f0.z, f0.w);
    __half2 h2 = __floats2half2_rn(f1.x, f1.y);
    __half2 h3 = __floats2half2_rn(f1.z, f1.w);
    uint4 o;
    o.x = *(unsigned*)&h0; o.y = *(unsigned*)&h1;
    o.z = *(unsigned*)&h2; o.w = *(unsigned*)&h3;
    dst[j] = o;
}

// gate + up + x (feeds k_gateup)
__global__ void k_cvt_gux(const float4* __restrict__ gate,
                          const float4* __restrict__ up,
                          const float4* __restrict__ x) {
    const int NW8 = NEXP * INTER * HID / 8;
    const int NX8 = NTOK * HID / 8;
    int total = 2 * NW8 + NX8;
    for (int i = blockIdx.x * blockDim.x + threadIdx.x; i < total;
         i += gridDim.x * blockDim.x) {
        if (i < NW8)          cvt8(gate, (uint4*)gh_gate, i);
        else if (i < 2 * NW8) cvt8(up,   (uint4*)gh_up,   i - NW8);
        else                  cvt8(x,    (uint4*)gh_x,    i - 2 * NW8);
    }
}

// down (feeds k_down; overlapped with k_gateup on side stream)
__global__ void k_cvt_down(const float4* __restrict__ down) {
    const int NW8 = NEXP * INTER * HID / 8;
    for (int i = blockIdx.x * blockDim.x + threadIdx.x; i < NW8;
         i += gridDim.x * blockDim.x)
        cvt8(down, (uint4*)gh_down, i);
}

// ---------------- kernel 3: fp16 MMA gate+up + SwiGLU (unchanged) --------
#define GU_A(s)  (0 + (s) * 256)
#define GU_G(s)  (768 + (s) * 512)
#define GU_U(s)  (2304 + (s) * 512)
#define GU_TOKB  (3840 * 16)
#define GU_SMEM  (3840 * 16 + TM * 8 + 16)

__global__ __launch_bounds__(256, 2) void k_gateup() {
    int tile = blockIdx.y;
    if (tile >= g_ntiles) return;
    int4 d = g_desc[tile];
    int e = d.x, rs = d.y, cnt = d.z, ib = d.w;
    int ctile = blockIdx.x * 128;

    extern __shared__ uint4 smem[];
    int*   s_tok = (int*)((char*)smem + GU_TOKB);
    float* s_w   = (float*)(s_tok + TM);

    int tid = threadIdx.x, lane = tid & 31, warp = tid >> 5;
    if (tid < TM) {
        s_tok[tid] = (tid < cnt) ? g_tok[e * NPAIR + rs + tid] : g_tok[e * NPAIR + rs];
        s_w[tid]   = (tid < cnt) ? g_wt[e * NPAIR + rs + tid] : 0.0f;
    }
    __syncthreads();

    int prow = tid >> 2, pg = tid & 3;
    const __half* aptr = gh_x + (size_t)s_tok[prow] * HID + pg * 8;
    const __half* gp0 = gh_gate + (size_t)e * INTER * HID + (size_t)(ctile + prow) * HID + pg * 8;
    const __half* gp1 = gp0 + (size_t)64 * HID;
    const __half* up0 = gh_up + (size_t)e * INTER * HID + (size_t)(ctile + prow) * HID + pg * 8;
    const __half* up1 = up0 + (size_t)64 * HID;
    int sw_lo = swzi(prow, pg);
    int sw_hi = swzi(prow + 64, pg);
    unsigned sbase = (unsigned)__cvta_generic_to_shared(smem);

    int mg = (warp & 1) * 32, nh = (warp >> 1) * 32;
    int ly = lane >> 2, lx = lane & 3;
    int arl = (lane & 7) + ((lane >> 3) & 1) * 8;
    int akb = (lane >> 4) & 1;
    int brl = (lane & 7) + ((lane >> 4) & 1) * 8;
    int bkb = (lane >> 3) & 1;

    float accg[2][4][4] = {}, accu[2][4][4] = {};

    const int NCH = HID / KC;   // 64
    #pragma unroll
    for (int s = 0; s < 2; s++) {
        int ko = s * KC;
        CP16(sbase + (GU_A(s) + sw_lo) * 16, aptr + ko);
        CP16(sbase + (GU_G(s) + sw_lo) * 16, gp0 + ko);
        CP16(sbase + (GU_G(s) + sw_hi) * 16, gp1 + ko);
        CP16(sbase + (GU_U(s) + sw_lo) * 16, up0 + ko);
        CP16(sbase + (GU_U(s) + sw_hi) * 16, up1 + ko);
        CP_COMMIT();
    }

    for (int c = 0; c < NCH; c++) {
        int p = c % 3;
        CP_WAIT1();
        __syncthreads();

        const uint4* bA = smem + GU_A(p);
        const uint4* bG = smem + GU_G(p);
        const uint4* bU = smem + GU_U(p);
        #pragma unroll
        for (int ks = 0; ks < 2; ks++) {
            int kg = ks * 2;
            unsigned a[2][4], b[2][4];
            ldm4(a[0][0], a[0][1], a[0][2], a[0][3], bA + swzi(mg + arl,      kg + akb));
            ldm4(a[1][0], a[1][1], a[1][2], a[1][3], bA + swzi(mg + 16 + arl, kg + akb));
            ldm4(b[0][0], b[0][1], b[0][2], b[0][3], bG + swzi(nh + brl,      kg + bkb));
            ldm4(b[1][0], b[1][1], b[1][2], b[1][3], bG + swzi(nh + 16 + brl, kg + bkb));
            #pragma unroll
            for (int mi = 0; mi < 2; mi++) {
                MMA_F16(accg[mi][0], a[mi], b[0][0], b[0][1]);
                MMA_F16(accg[mi][1], a[mi], b[0][2], b[0][3]);
                MMA_F16(accg[mi][2], a[mi], b[1][0], b[1][1]);
                MMA_F16(accg[mi][3], a[mi], b[1][2], b[1][3]);
            }
            ldm4(b[0][0], b[0][1], b[0][2], b[0][3], bU + swzi(nh + brl,      kg + bkb));
            ldm4(b[1][0], b[1][1], b[1][2], b[1][3], bU + swzi(nh + 16 + brl, kg + bkb));
            #pragma unroll
            for (int mi = 0; mi < 2; mi++) {
                MMA_F16(accu[mi][0], a[mi], b[0][0], b[0][1]);
                MMA_F16(accu[mi][1], a[mi], b[0][2], b[0][3]);
                MMA_F16(accu[mi][2], a[mi], b[1][0], b[1][1]);
                MMA_F16(accu[mi][3], a[mi], b[1][2], b[1][3]);
            }
        }
        if (c + 2 < NCH) {
            int s = (c + 2) % 3;
            int ko = (c + 2) * KC;
            CP16(sbase + (GU_A(s) + sw_lo) * 16, aptr + ko);
            CP16(sbase + (GU_G(s) + sw_lo) * 16, gp0 + ko);
            CP16(sbase + (GU_G(s) + sw_hi) * 16, gp1 + ko);
            CP16(sbase + (GU_U(s) + sw_lo) * 16, up0 + ko);
            CP16(sbase + (GU_U(s) + sw_hi) * 16, up1 + ko);
        }
        CP_COMMIT();
    }

    #pragma unroll
    for (int mi = 0; mi < 2; mi++) {
        int r0 = mg + mi * 16 + ly, r1 = r0 + 8;
        #pragma unroll
        for (int nj = 0; nj < 4; nj++) {
            int cc = ctile + nh + nj * 8 + 2 * lx;
            if (r0 < cnt) {
                float w = s_w[r0];
                float ga = accg[mi][nj][0], ua = accu[mi][nj][0];
                float gb = accg[mi][nj][1], ub = accu[mi][nj][1];
                float o0 = ga / (1.0f + __expf(-ga)) * ua * w;
                float o1 = gb / (1.0f + __expf(-gb)) * ub * w;
                *(__half2*)&g_inter[(size_t)(ib + r0) * INTER + cc] = __floats2half2_rn(o0, o1);
            }
            if (r1 < cnt) {
                float w = s_w[r1];
                float ga = accg[mi][nj][2], ua = accu[mi][nj][2];
                float gb = accg[mi][nj][3], ub = accu[mi][nj][3];
                float o0 = ga / (1.0f + __expf(-ga)) * ua * w;
                float o1 = gb / (1.0f + __expf(-gb)) * ub * w;
                *(__half2*)&g_inter[(size_t)(ib + r1) * INTER + cc] = __floats2half2_rn(o0, o1);
            }
        }
    }
}

// ---------------- kernel 4: fp16 MMA down + scatter-add (unchanged) ------
#define DN_A(s)  (0 + (s) * 256)
#define DN_B(s)  (768 + (s) * 512)
#define DN_TOKB  (2304 * 16)
#define DN_SMEM  (2304 * 16 + TM * 4 + 16)

__global__ __launch_bounds__(256, 2) void k_down(float* __restrict__ out) {
    int tile = blockIdx.y;
    if (tile >= g_ntiles) return;
    int4 d = g_desc[tile];
    int e = d.x, rs = d.y, cnt = d.z, ib = d.w;
    int ctile = blockIdx.x * 128;

    extern __shared__ uint4 smem[];
    int* s_tok = (int*)((char*)smem + DN_TOKB);

    int tid = threadIdx.x, lane = tid & 31, warp = tid >> 5;
    if (tid < TM)
        s_tok[tid] = (tid < cnt) ? g_tok[e * NPAIR + rs + tid] : 0;
    __syncthreads();

    int prow = tid >> 2, pg = tid & 3;
    const __half* aptr = g_inter + (size_t)(ib + prow) * INTER + pg * 8;
    const __half* bp0 = gh_down + (size_t)e * HID * INTER + (size_t)(ctile + prow) * INTER + pg * 8;
    const __half* bp1 = bp0 + (size_t)64 * INTER;
    int sw_lo = swzi(prow, pg);
    int sw_hi = swzi(prow + 64, pg);
    unsigned sbase = (unsigned)__cvta_generic_to_shared(smem);

    int mg = (warp & 1) * 32, nh = (warp >> 1) * 32;
    int ly = lane >> 2, lx = lane & 3;
    int arl = (lane & 7) + ((lane >> 3) & 1) * 8;
    int akb = (lane >> 4) & 1;
    int brl = (lane & 7) + ((lane >> 4) & 1) * 8;
    int bkb = (lane >> 3) & 1;

    float acc[2][4][4] = {};

    const int NCH = INTER / KC;   // 32
    #pragma unroll
    for (int s = 0; s < 2; s++) {
        int ko = s * KC;
        CP16(sbase + (DN_A(s) + sw_lo) * 16, aptr + ko);
        CP16(sbase + (DN_B(s) + sw_lo) * 16, bp0 + ko);
        CP16(sbase + (DN_B(s) + sw_hi) * 16, bp1 + ko);
        CP_COMMIT();
    }

    for (int c = 0; c < NCH; c++) {
        int p = c % 3;
        CP_WAIT1();
        __syncthreads();

        const uint4* bA = smem + DN_A(p);
        const uint4* bB = smem + DN_B(p);
        #pragma unroll
        for (int ks = 0; ks < 2; ks++) {
            int kg = ks * 2;
            unsigned a[2][4], b[2][4];
            ldm4(a[0][0], a[0][1], a[0][2], a[0][3], bA + swzi(mg + arl,      kg + akb));
            ldm4(a[1][0], a[1][1], a[1][2], a[1][3], bA + swzi(mg + 16 + arl, kg + akb));
            ldm4(b[0][0], b[0][1], b[0][2], b[0][3], bB + swzi(nh + brl,      kg + bkb));
            ldm4(b[1][0], b[1][1], b[1][2], b[1][3], bB + swzi(nh + 16 + brl, kg + bkb));
            #pragma unroll
            for (int mi = 0; mi < 2; mi++) {
                MMA_F16(acc[mi][0], a[mi], b[0][0], b[0][1]);
                MMA_F16(acc[mi][1], a[mi], b[0][2], b[0][3]);
                MMA_F16(acc[mi][2], a[mi], b[1][0], b[1][1]);
                MMA_F16(acc[mi][3], a[mi], b[1][2], b[1][3]);
            }
        }
        if (c + 2 < NCH) {
            int s = (c + 2) % 3;
            int ko = (c + 2) * KC;
            CP16(sbase + (DN_A(s) + sw_lo) * 16, aptr + ko);
            CP16(sbase + (DN_B(s) + sw_lo) * 16, bp0 + ko);
            CP16(sbase + (DN_B(s) + sw_hi) * 16, bp1 + ko);
        }
        CP_COMMIT();
    }

    #pragma unroll
    for (int mi = 0; mi < 2; mi++) {
        int r0 = mg + mi * 16 + ly, r1 = r0 + 8;
        #pragma unroll
        for (int nj = 0; nj < 4; nj++) {
            int cc = ctile + nh + nj * 8 + 2 * lx;
            if (r0 < cnt) {
                float* o = out + (size_t)s_tok[r0] * HID + cc;
                atomicAdd(o,     acc[mi][nj][0]);
                atomicAdd(o + 1, acc[mi][nj][1]);
            }
            if (r1 < cnt) {
                float* o = out + (size_t)s_tok[r1] * HID + cc;
                atomicAdd(o,     acc[mi][nj][2]);
                atomicAdd(o + 1, acc[mi][nj][3]);
            }
        }
    }
}

// ---------------- launch: fork AFTER cvt_gux (overlap with gateup) -------
extern "C" void kernel_launch(void* const* d_in, const int* in_sizes, int n_in,
                              void* d_out, int out_size) {
    const float* x    = (const float*)d_in[0];
    const int*   eidx = (const int*)d_in[1];
    const float* ewt  = (const float*)d_in[2];
    const float* gate = (const float*)d_in[3];
    const float* up   = (const float*)d_in[4];
    const float* down = (const float*)d_in[5];
    float* out = (float*)d_out;

    cudaFuncSetAttribute(k_gateup, cudaFuncAttributeMaxDynamicSharedMemorySize, GU_SMEM);
    cudaFuncSetAttribute(k_down,   cudaFuncAttributeMaxDynamicSharedMemorySize, DN_SMEM);

    cudaStream_t s2;
    cudaStreamCreateWithFlags(&s2, cudaStreamNonBlocking);
    cudaEvent_t eFork, eJoin;
    cudaEventCreateWithFlags(&eFork, cudaEventDisableTiming);
    cudaEventCreateWithFlags(&eJoin, cudaEventDisableTiming);

    // main: routing + gate/up/x cvt (DRAM-bound phase, keep bus to itself)
    k_cnt0<<<1, 32>>>();
    k_route<<<(NPAIR + 255) / 256, 256>>>(eidx, ewt);
    k_desc<<<1, 32>>>();
    k_cvt_gux<<<8192, 256>>>((const float4*)gate, (const float4*)up,
                             (const float4*)x);

    // fork AFTER cvt_gux: side branch runs under gateup's DRAM-idle window
    cudaEventRecord(eFork, 0);
    cudaStreamWaitEvent(s2, eFork, 0);
    k_zero_out<<<2048, 256, 0, s2>>>((float4*)out);
    k_cvt_down<<<4096, 256, 0, s2>>>((const float4*)down);
    cudaEventRecord(eJoin, s2);

    // main: gateup GEMM (smem/tensor-bound, DRAM mostly idle)
    dim3 g2(INTER / 128, 72);
    k_gateup<<<g2, 256, GU_SMEM>>>();

    // join: down needs zeroed out + converted down-weights + g_inter
    cudaStreamWaitEvent(0, eJoin, 0);
    dim3 g3(HID / 128, 72);
    k_down<<<g3, 256, DN_SMEM>>>(out);
}

// round 13
// speedup vs baseline: 1.5805x; 1.0283x over previous
#include <cuda_runtime.h>
#include <cuda_fp16.h>
#include <math.h>
#include <cstdint>

// Problem constants
#define HID 2048
#define INTER 1024
#define NEXP 8
#define NTOK 2048
#define TOPK 2
#define NPAIR (NTOK * TOPK)   // 4096

#define TM 64                 // pair-rows per tile
#define KC 32                 // K halves per chunk (64B per logical row)

// ---------------- device scratch ----------------
__device__ int    g_cnt[NEXP];
__device__ int    g_tok[NEXP * NPAIR];
__device__ float  g_wt[NEXP * NPAIR];
__device__ int4   g_desc[96];             // {expert, row_start, count, inter_base}
__device__ int    g_ntiles;
__device__ __half gh_x[NTOK * HID];
__device__ __half gh_gate[NEXP * INTER * HID];
__device__ __half gh_up[NEXP * INTER * HID];
__device__ __half gh_down[NEXP * HID * INTER];
__device__ __half g_inter[(NPAIR + TM) * INTER];

// ---------------- helpers ----------------
__device__ __forceinline__ void ldm4(unsigned& r0, unsigned& r1, unsigned& r2,
                                     unsigned& r3, const void* ptr) {
    unsigned addr = (unsigned)__cvta_generic_to_shared(ptr);
    asm volatile("ldmatrix.sync.aligned.m8n8.x4.shared.b16 {%0,%1,%2,%3}, [%4];"
                 : "=r"(r0), "=r"(r1), "=r"(r2), "=r"(r3) : "r"(addr));
}

#define MMA_F16(c, a, b0, b1)                                                 \
    asm volatile(                                                             \
        "mma.sync.aligned.m16n8k16.row.col.f32.f16.f16.f32 "                  \
        "{%0,%1,%2,%3}, {%4,%5,%6,%7}, {%8,%9}, {%0,%1,%2,%3};"               \
        : "+f"((c)[0]), "+f"((c)[1]), "+f"((c)[2]), "+f"((c)[3])              \
        : "r"((a)[0]), "r"((a)[1]), "r"((a)[2]), "r"((a)[3]), "r"(b0), "r"(b1))

#define CP16(dst, src)                                                        \
    asm volatile("cp.async.cg.shared.global [%0], [%1], 16;"                  \
                 :: "r"(dst), "l"(src))
#define CP_COMMIT() asm volatile("cp.async.commit_group;" ::: "memory")
#define CP_WAIT1()  asm volatile("cp.async.wait_group 1;" ::: "memory")

// Paired-row XOR swizzle: (row, 16B-group g in 0..3) -> uint4 index.
__device__ __forceinline__ int swzi(int row, int g) {
    int srow = row >> 1;
    return srow * 8 + ((((row & 1) << 2) | g) ^ (srow & 7));
}

// ---------------- small setup kernels ----------------
__global__ void k_cnt0() {
    if (threadIdx.x < NEXP) g_cnt[threadIdx.x] = 0;
}

__global__ void k_zero_out(float4* out) {
    int i = blockIdx.x * blockDim.x + threadIdx.x;
    int total = NTOK * HID / 4;
    for (; i < total; i += gridDim.x * blockDim.x)
        out[i] = make_float4(0.f, 0.f, 0.f, 0.f);
}

__global__ void k_route(const int* __restrict__ idx,
                        const float* __restrict__ wts) {
    int p = blockIdx.x * blockDim.x + threadIdx.x;
    if (p >= NPAIR) return;
    int e = idx[p] & 7;
    float w = wts[p];
    int pos = atomicAdd(&g_cnt[e], 1);
    g_tok[e * NPAIR + pos] = p >> 1;   // token id
    g_wt[e * NPAIR + pos] = w;
}

__global__ void k_desc() {
    if (threadIdx.x != 0 || blockIdx.x != 0) return;
    int nt = 0, base = 0;
    for (int e = 0; e < NEXP; e++) {
        int c = g_cnt[e];
        for (int s = 0; s < c; s += TM) {
            int rows = c - s; if (rows > TM) rows = TM;
            g_desc[nt] = make_int4(e, s, rows, base + s);
            nt++;
        }
        base += c;
    }
    g_ntiles = nt;
}

// ---------------- cvt kernels (split by consumer) ----------------
__device__ __forceinline__ void cvt8(const float4* src, uint4* dst, int j) {
    float4 f0 = src[2 * j], f1 = src[2 * j + 1];
    __half2 h0 = __floats2half2_rn(f0.x, f0.y);
    __half2 h1 = __floats2half2_rn(f0.z, f0.w);
    __half2 h2 = __floats2half2_rn(f1.x, f1.y);
    __half2 h3 = __floats2half2_rn(f1.z, f1.w);
    uint4 o;
    o.x = *(unsigned*)&h0; o.y = *(unsigned*)&h1;
    o.z = *(unsigned*)&h2; o.w = *(unsigned*)&h3;
    dst[j] = o;
}

__global__ void k_cvt_gux(const float4* __restrict__ gate,
                          const float4* __restrict__ up,
                          const float4* __restrict__ x) {
    const int NW8 = NEXP * INTER * HID / 8;
    const int NX8 = NTOK * HID / 8;
    int total = 2 * NW8 + NX8;
    for (int i = blockIdx.x * blockDim.x + threadIdx.x; i < total;
         i += gridDim.x * blockDim.x) {
        if (i < NW8)          cvt8(gate, (uint4*)gh_gate, i);
        else if (i < 2 * NW8) cvt8(up,   (uint4*)gh_up,   i - NW8);
        else                  cvt8(x,    (uint4*)gh_x,    i - 2 * NW8);
    }
}

__global__ void k_cvt_down(const float4* __restrict__ down) {
    const int NW8 = NEXP * INTER * HID / 8;
    for (int i = blockIdx.x * blockDim.x + threadIdx.x; i < NW8;
         i += gridDim.x * blockDim.x)
        cvt8(down, (uint4*)gh_down, i);
}

// ---------------- kernel 3: fp16 MMA gate+up + SwiGLU (unchanged) --------
#define GU_A(s)  (0 + (s) * 256)
#define GU_G(s)  (768 + (s) * 512)
#define GU_U(s)  (2304 + (s) * 512)
#define GU_TOKB  (3840 * 16)
#define GU_SMEM  (3840 * 16 + TM * 8 + 16)

__global__ __launch_bounds__(256, 2) void k_gateup() {
    int tile = blockIdx.y;
    if (tile >= g_ntiles) return;
    int4 d = g_desc[tile];
    int e = d.x, rs = d.y, cnt = d.z, ib = d.w;
    int ctile = blockIdx.x * 128;

    extern __shared__ uint4 smem[];
    int*   s_tok = (int*)((char*)smem + GU_TOKB);
    float* s_w   = (float*)(s_tok + TM);

    int tid = threadIdx.x, lane = tid & 31, warp = tid >> 5;
    if (tid < TM) {
        s_tok[tid] = (tid < cnt) ? g_tok[e * NPAIR + rs + tid] : g_tok[e * NPAIR + rs];
        s_w[tid]   = (tid < cnt) ? g_wt[e * NPAIR + rs + tid] : 0.0f;
    }
    __syncthreads();

    int prow = tid >> 2, pg = tid & 3;
    const __half* aptr = gh_x + (size_t)s_tok[prow] * HID + pg * 8;
    const __half* gp0 = gh_gate + (size_t)e * INTER * HID + (size_t)(ctile + prow) * HID + pg * 8;
    const __half* gp1 = gp0 + (size_t)64 * HID;
    const __half* up0 = gh_up + (size_t)e * INTER * HID + (size_t)(ctile + prow) * HID + pg * 8;
    const __half* up1 = up0 + (size_t)64 * HID;
    int sw_lo = swzi(prow, pg);
    int sw_hi = swzi(prow + 64, pg);
    unsigned sbase = (unsigned)__cvta_generic_to_shared(smem);

    int mg = (warp & 1) * 32, nh = (warp >> 1) * 32;
    int ly = lane >> 2, lx = lane & 3;
    int arl = (lane & 7) + ((lane >> 3) & 1) * 8;
    int akb = (lane >> 4) & 1;
    int brl = (lane & 7) + ((lane >> 4) & 1) * 8;
    int bkb = (lane >> 3) & 1;

    float accg[2][4][4] = {}, accu[2][4][4] = {};

    const int NCH = HID / KC;   // 64
    #pragma unroll
    for (int s = 0; s < 2; s++) {
        int ko = s * KC;
        CP16(sbase + (GU_A(s) + sw_lo) * 16, aptr + ko);
        CP16(sbase + (GU_G(s) + sw_lo) * 16, gp0 + ko);
        CP16(sbase + (GU_G(s) + sw_hi) * 16, gp1 + ko);
        CP16(sbase + (GU_U(s) + sw_lo) * 16, up0 + ko);
        CP16(sbase + (GU_U(s) + sw_hi) * 16, up1 + ko);
        CP_COMMIT();
    }

    for (int c = 0; c < NCH; c++) {
        int p = c % 3;
        CP_WAIT1();
        __syncthreads();

        const uint4* bA = smem + GU_A(p);
        const uint4* bG = smem + GU_G(p);
        const uint4* bU = smem + GU_U(p);
        #pragma unroll
        for (int ks = 0; ks < 2; ks++) {
            int kg = ks * 2;
            unsigned a[2][4], b[2][4];
            ldm4(a[0][0], a[0][1], a[0][2], a[0][3], bA + swzi(mg + arl,      kg + akb));
            ldm4(a[1][0], a[1][1], a[1][2], a[1][3], bA + swzi(mg + 16 + arl, kg + akb));
            ldm4(b[0][0], b[0][1], b[0][2], b[0][3], bG + swzi(nh + brl,      kg + bkb));
            ldm4(b[1][0], b[1][1], b[1][2], b[1][3], bG + swzi(nh + 16 + brl, kg + bkb));
            #pragma unroll
            for (int mi = 0; mi < 2; mi++) {
                MMA_F16(accg[mi][0], a[mi], b[0][0], b[0][1]);
                MMA_F16(accg[mi][1], a[mi], b[0][2], b[0][3]);
                MMA_F16(accg[mi][2], a[mi], b[1][0], b[1][1]);
                MMA_F16(accg[mi][3], a[mi], b[1][2], b[1][3]);
            }
            ldm4(b[0][0], b[0][1], b[0][2], b[0][3], bU + swzi(nh + brl,      kg + bkb));
            ldm4(b[1][0], b[1][1], b[1][2], b[1][3], bU + swzi(nh + 16 + brl, kg + bkb));
            #pragma unroll
            for (int mi = 0; mi < 2; mi++) {
                MMA_F16(accu[mi][0], a[mi], b[0][0], b[0][1]);
                MMA_F16(accu[mi][1], a[mi], b[0][2], b[0][3]);
                MMA_F16(accu[mi][2], a[mi], b[1][0], b[1][1]);
                MMA_F16(accu[mi][3], a[mi], b[1][2], b[1][3]);
            }
        }
        if (c + 2 < NCH) {
            int s = (c + 2) % 3;
            int ko = (c + 2) * KC;
            CP16(sbase + (GU_A(s) + sw_lo) * 16, aptr + ko);
            CP16(sbase + (GU_G(s) + sw_lo) * 16, gp0 + ko);
            CP16(sbase + (GU_G(s) + sw_hi) * 16, gp1 + ko);
            CP16(sbase + (GU_U(s) + sw_lo) * 16, up0 + ko);
            CP16(sbase + (GU_U(s) + sw_hi) * 16, up1 + ko);
        }
        CP_COMMIT();
    }

    #pragma unroll
    for (int mi = 0; mi < 2; mi++) {
        int r0 = mg + mi * 16 + ly, r1 = r0 + 8;
        #pragma unroll
        for (int nj = 0; nj < 4; nj++) {
            int cc = ctile + nh + nj * 8 + 2 * lx;
            if (r0 < cnt) {
                float w = s_w[r0];
                float ga = accg[mi][nj][0], ua = accu[mi][nj][0];
                float gb = accg[mi][nj][1], ub = accu[mi][nj][1];
                float o0 = ga / (1.0f + __expf(-ga)) * ua * w;
                float o1 = gb / (1.0f + __expf(-gb)) * ub * w;
                *(__half2*)&g_inter[(size_t)(ib + r0) * INTER + cc] = __floats2half2_rn(o0, o1);
            }
            if (r1 < cnt) {
                float w = s_w[r1];
                float ga = accg[mi][nj][2], ua = accu[mi][nj][2];
                float gb = accg[mi][nj][3], ub = accu[mi][nj][3];
                float o0 = ga / (1.0f + __expf(-ga)) * ua * w;
                float o1 = gb / (1.0f + __expf(-gb)) * ub * w;
                *(__half2*)&g_inter[(size_t)(ib + r1) * INTER + cc] = __floats2half2_rn(o0, o1);
            }
        }
    }
}

// ---------------- kernel 4: fp16 MMA down (64x256 block, warp 32x64) -----
#define DN_A(s)  (0 + (s) * 256)
#define DN_B(s)  (768 + (s) * 1024)
#define DN_TOKB  (3840 * 16)
#define DN_SMEM  (3840 * 16 + TM * 4 + 16)

__global__ __launch_bounds__(256, 2) void k_down(float* __restrict__ out) {
    int tile = blockIdx.y;
    if (tile >= g_ntiles) return;
    int4 d = g_desc[tile];
    int e = d.x, rs = d.y, cnt = d.z, ib = d.w;
    int ctile = blockIdx.x * 256;

    extern __shared__ uint4 smem[];
    int* s_tok = (int*)((char*)smem + DN_TOKB);

    int tid = threadIdx.x, lane = tid & 31, warp = tid >> 5;
    if (tid < TM)
        s_tok[tid] = (tid < cnt) ? g_tok[e * NPAIR + rs + tid] : 0;
    __syncthreads();

    int prow = tid >> 2, pg = tid & 3;
    const __half* aptr = g_inter + (size_t)(ib + prow) * INTER + pg * 8;
    const __half* bp0 = gh_down + (size_t)e * HID * INTER + (size_t)(ctile + prow) * INTER + pg * 8;
    int sw0 = swzi(prow, pg);
    int sw1 = swzi(prow + 64, pg);
    int sw2 = swzi(prow + 128, pg);
    int sw3 = swzi(prow + 192, pg);
    unsigned sbase = (unsigned)__cvta_generic_to_shared(smem);

    int mg = (warp & 1) * 32, nh = (warp >> 1) * 64;
    int ly = lane >> 2, lx = lane & 3;
    int arl = (lane & 7) + ((lane >> 3) & 1) * 8;
    int akb = (lane >> 4) & 1;
    int brl = (lane & 7) + ((lane >> 4) & 1) * 8;
    int bkb = (lane >> 3) & 1;

    float acc[2][8][4] = {};

    const int NCH = INTER / KC;   // 32
    #pragma unroll
    for (int s = 0; s < 2; s++) {
        int ko = s * KC;
        CP16(sbase + (DN_A(s) + sw0) * 16, aptr + ko);
        CP16(sbase + (DN_B(s) + sw0) * 16, bp0 + ko);
        CP16(sbase + (DN_B(s) + sw1) * 16, bp0 + ko + (size_t)64 * INTER);
        CP16(sbase + (DN_B(s) + sw2) * 16, bp0 + ko + (size_t)128 * INTER);
        CP16(sbase + (DN_B(s) + sw3) * 16, bp0 + ko + (size_t)192 * INTER);
        CP_COMMIT();
    }

    for (int c = 0; c < NCH; c++) {
        int p = c % 3;
        CP_WAIT1();
        __syncthreads();

        const uint4* bA = smem + DN_A(p);
        const uint4* bB = smem + DN_B(p);
        #pragma unroll
        for (int ks = 0; ks < 2; ks++) {
            int kg = ks * 2;
            unsigned a[2][4], b[4][4];
            ldm4(a[0][0], a[0][1], a[0][2], a[0][3], bA + swzi(mg + arl,      kg + akb));
            ldm4(a[1][0], a[1][1], a[1][2], a[1][3], bA + swzi(mg + 16 + arl, kg + akb));
            #pragma unroll
            for (int nb = 0; nb < 4; nb++)
                ldm4(b[nb][0], b[nb][1], b[nb][2], b[nb][3],
                     bB + swzi(nh + 16 * nb + brl, kg + bkb));
            #pragma unroll
            for (int mi = 0; mi < 2; mi++)
                #pragma unroll
                for (int nb = 0; nb < 4; nb++) {
                    MMA_F16(acc[mi][2 * nb],     a[mi], b[nb][0], b[nb][1]);
                    MMA_F16(acc[mi][2 * nb + 1], a[mi], b[nb][2], b[nb][3]);
                }
        }
        if (c + 2 < NCH) {
            int s = (c + 2) % 3;
            int ko = (c + 2) * KC;
            CP16(sbase + (DN_A(s) + sw0) * 16, aptr + ko);
            CP16(sbase + (DN_B(s) + sw0) * 16, bp0 + ko);
            CP16(sbase + (DN_B(s) + sw1) * 16, bp0 + ko + (size_t)64 * INTER);
            CP16(sbase + (DN_B(s) + sw2) * 16, bp0 + ko + (size_t)128 * INTER);
            CP16(sbase + (DN_B(s) + sw3) * 16, bp0 + ko + (size_t)192 * INTER);
        }
        CP_COMMIT();
    }

    #pragma unroll
    for (int mi = 0; mi < 2; mi++) {
        int r0 = mg + mi * 16 + ly, r1 = r0 + 8;
        #pragma unroll
        for (int nj = 0; nj < 8; nj++) {
            int cc = ctile + nh + nj * 8 + 2 * lx;
            if (r0 < cnt) {
                float* o = out + (size_t)s_tok[r0] * HID + cc;
                atomicAdd(o,     acc[mi][nj][0]);
                atomicAdd(o + 1, acc[mi][nj][1]);
            }
            if (r1 < cnt) {
                float* o = out + (size_t)s_tok[r1] * HID + cc;
                atomicAdd(o,     acc[mi][nj][2]);
                atomicAdd(o + 1, acc[mi][nj][3]);
            }
        }
    }
}

// ---------------- launch: single-fork schedule (R11 topology) ------------
extern "C" void kernel_launch(void* const* d_in, const int* in_sizes, int n_in,
                              void* d_out, int out_size) {
    const float* x    = (const float*)d_in[0];
    const int*   eidx = (const int*)d_in[1];
    const float* ewt  = (const float*)d_in[2];
    const float* gate = (const float*)d_in[3];
    const float* up   = (const float*)d_in[4];
    const float* down = (const float*)d_in[5];
    float* out = (float*)d_out;

    cudaFuncSetAttribute(k_gateup, cudaFuncAttributeMaxDynamicSharedMemorySize, GU_SMEM);
    cudaFuncSetAttribute(k_down,   cudaFuncAttributeMaxDynamicSharedMemorySize, DN_SMEM);

    cudaStream_t s2;
    cudaStreamCreateWithFlags(&s2, cudaStreamNonBlocking);
    cudaEvent_t eFork, eJoin;
    cudaEventCreateWithFlags(&eFork, cudaEventDisableTiming);
    cudaEventCreateWithFlags(&eJoin, cudaEventDisableTiming);

    // main: routing + gate/up/x cvt (DRAM-bound phase, keep bus to itself)
    k_cnt0<<<1, 32>>>();
    k_route<<<(NPAIR + 255) / 256, 256>>>(eidx, ewt);
    k_desc<<<1, 32>>>();
    k_cvt_gux<<<8192, 256>>>((const float4*)gate, (const float4*)up,
                             (const float4*)x);

    // fork AFTER cvt_gux: side branch runs under gateup's DRAM-idle window
    cudaEventRecord(eFork, 0);
    cudaStreamWaitEvent(s2, eFork, 0);
    k_zero_out<<<2048, 256, 0, s2>>>((float4*)out);
    k_cvt_down<<<4096, 256, 0, s2>>>((const float4*)down);
    cudaEventRecord(eJoin, s2);

    // main: gateup GEMM (smem/tensor-bound, DRAM mostly idle)
    dim3 g2(INTER / 128, 72);
    k_gateup<<<g2, 256, GU_SMEM>>>();

    // join: down needs zeroed out + converted down-weights + g_inter
    cudaStreamWaitEvent(0, eJoin, 0);
    dim3 g3(HID / 256, 72);
    k_down<<<g3, 256, DN_SMEM>>>(out);
}